// round 14
// baseline (speedup 1.0000x reference)
#include <cuda_runtime.h>
#include <cuda_bf16.h>
#include <mma.h>
#include <cstdint>

using namespace nvcuda;

#define BB 32
#define SS 2048
#define DD 1024
#define CH 16
#define SC (SS/CH)

// ---------------- device scratch (no allocs allowed) ----------------
__device__ __nv_bfloat16 g_xb[(size_t)BB * SS * DD];   // bf16 x, row-major [b][s][d]
__device__ float g_psum[BB * CH * DD];
__device__ float g_psq [BB * CH * DD];
__device__ float g_mean[BB * DD];
__device__ float g_var [BB * DD];
__device__ float g_keep[BB * DD];

__device__ __forceinline__ uint32_t smem_u32(const void* p) {
    uint32_t a;
    asm("{ .reg .u64 t; cvta.to.shared.u64 t, %1; cvt.u32.u64 %0, t; }" : "=r"(a) : "l"(p));
    return a;
}
#define CP_ASYNC16(sm, gm) \
    asm volatile("cp.async.cg.shared.global [%0], [%1], 16;" :: "r"(sm), "l"(gm) : "memory")
#define CP_COMMIT()   asm volatile("cp.async.commit_group;" ::: "memory")
#define CP_WAIT(n)    asm volatile("cp.async.wait_group %0;" :: "n"(n) : "memory")

// =====================================================================
// Kernel 1: per-(b, s-chunk) column partial sums + fp32->bf16 convert
// =====================================================================
__global__ void __launch_bounds__(256) stats_convert_kernel(const float* __restrict__ x) {
    int b = blockIdx.x / CH;
    int c = blockIdx.x % CH;
    int d0 = threadIdx.x * 4;

    float s0 = 0.f, s1 = 0.f, s2 = 0.f, s3 = 0.f;
    float q0 = 0.f, q1 = 0.f, q2 = 0.f, q3 = 0.f;

    #pragma unroll 4
    for (int r = 0; r < SC; ++r) {
        size_t off = ((size_t)b * SS + (size_t)c * SC + r) * DD + d0;
        float4 v = *(const float4*)(x + off);
        s0 += v.x; s1 += v.y; s2 += v.z; s3 += v.w;
        q0 += v.x * v.x; q1 += v.y * v.y; q2 += v.z * v.z; q3 += v.w * v.w;
        __nv_bfloat162 lo = __floats2bfloat162_rn(v.x, v.y);
        __nv_bfloat162 hi = __floats2bfloat162_rn(v.z, v.w);
        uint2 pk;
        pk.x = *(const unsigned int*)&lo;
        pk.y = *(const unsigned int*)&hi;
        *(uint2*)(g_xb + off) = pk;
    }
    int p = (b * CH + c) * DD + d0;
    *(float4*)(g_psum + p) = make_float4(s0, s1, s2, s3);
    *(float4*)(g_psq  + p) = make_float4(q0, q1, q2, q3);
}

// =====================================================================
// Kernel 2: reduce partials -> mean/var, init keep=1
// =====================================================================
__global__ void finalize_stats_kernel() {
    int i = blockIdx.x * 256 + threadIdx.x;
    int b = i >> 10, d = i & 1023;
    float s = 0.f, q = 0.f;
    #pragma unroll
    for (int c = 0; c < CH; ++c) {
        s += g_psum[(b * CH + c) * DD + d];
        q += g_psq [(b * CH + c) * DD + d];
    }
    float mean = s * (1.0f / SS);
    float var  = (q - (float)SS * mean * mean) * (1.0f / (SS - 1));
    g_mean[i] = mean; g_var[i] = var; g_keep[i] = 1.0f;
}

// =====================================================================
// Kernel 3: HMMA Gram, 128x128 tiles, 4-stage cp.async pipeline
//   8 warps in 2x4 grid; warp tile = 64(i) x 32(j)
//   smem stage: A[32k][128i] + B[32k][128j], pitch 136 bf16 (272B)
// =====================================================================
#define KB      32                      // k per slab
#define NSLAB   (SS / KB)               // 64
#define PITCH   136                     // bf16 elems per smem row
#define TBYTES  (KB * PITCH * 2)        // 8704 per tile
#define STAGEB  (2 * TBYTES)            // 17408
#define STAGES  4
#define DYNSMEM (STAGES * STAGEB)       // 69632 (C tile 128*132*4=67584 aliases)

// 36 upper-triangle pairs of 128-wide tiles over D=1024 (8 tiles)
__constant__ int c_bi[36] = {0, 0,1, 0,1,2, 0,1,2,3, 0,1,2,3,4, 0,1,2,3,4,5,
                             0,1,2,3,4,5,6, 0,1,2,3,4,5,6,7};
__constant__ int c_bj[36] = {0, 1,1, 2,2,2, 3,3,3,3, 4,4,4,4,4, 5,5,5,5,5,5,
                             6,6,6,6,6,6,6, 7,7,7,7,7,7,7,7};

__global__ void __launch_bounds__(256, 2) gram_kernel() {
    extern __shared__ __align__(16) uint8_t dyn[];
    __shared__ float s_mi[128], s_vi[128], s_mj[128], s_vj[128];

    int t = threadIdx.x, wid = t >> 5;
    int wm = wid >> 2;              // 0..1 -> 64-row half
    int wn = wid & 3;               // 0..3 -> 32-col quarter
    int b  = blockIdx.y;
    int i0 = c_bi[blockIdx.x] * 128;
    int j0 = c_bj[blockIdx.x] * 128;

    if (t < 128) {
        s_mi[t] = g_mean[b * DD + i0 + t];
        s_vi[t] = g_var [b * DD + i0 + t];
        s_mj[t] = g_mean[b * DD + j0 + t];
        s_vj[t] = g_var [b * DD + j0 + t];
    }

    const __nv_bfloat16* xb = g_xb + (size_t)b * SS * DD;
    uint32_t sbase = smem_u32(dyn);

    // per-thread chunk mapping: 4 chunks of 16B, c = i*256 + t
    //   tile = c>>9 (0=A/bi, 1=B/bj), r = (c>>4)&31, ch = c&15
    auto issue_slab = [&](int kc) {
        #pragma unroll
        for (int i = 0; i < 4; ++i) {
            int c    = i * 256 + t;
            int tile = c >> 9;
            int r    = (c >> 4) & 31;
            int ch   = c & 15;
            int dbase = (tile ? j0 : i0);
            const __nv_bfloat16* gp = xb + (size_t)(kc * KB + r) * DD + dbase + ch * 8;
            uint32_t sp = sbase + (uint32_t)((kc & (STAGES - 1)) * STAGEB
                                             + tile * TBYTES + r * (PITCH * 2) + ch * 16);
            CP_ASYNC16(sp, gp);
        }
        CP_COMMIT();
    };

    issue_slab(0); issue_slab(1); issue_slab(2);

    wmma::fragment<wmma::accumulator, 16, 16, 16, float> acc[4][2];
    #pragma unroll
    for (int x = 0; x < 4; ++x)
        #pragma unroll
        for (int y = 0; y < 2; ++y) wmma::fill_fragment(acc[x][y], 0.0f);

    for (int kc = 0; kc < NSLAB; ++kc) {
        CP_WAIT(2);
        __syncthreads();
        if (kc + 3 < NSLAB) issue_slab(kc + 3);

        const __nv_bfloat16* As = (const __nv_bfloat16*)(dyn + (kc & (STAGES - 1)) * STAGEB);
        const __nv_bfloat16* Bs = As + KB * PITCH;

        #pragma unroll
        for (int k2 = 0; k2 < KB; k2 += 16) {
            wmma::fragment<wmma::matrix_a, 16, 16, 16, __nv_bfloat16, wmma::col_major> a[4];
            wmma::fragment<wmma::matrix_b, 16, 16, 16, __nv_bfloat16, wmma::row_major> bf[2];
            #pragma unroll
            for (int x = 0; x < 4; ++x)
                wmma::load_matrix_sync(a[x], As + k2 * PITCH + wm * 64 + x * 16, PITCH);
            #pragma unroll
            for (int y = 0; y < 2; ++y)
                wmma::load_matrix_sync(bf[y], Bs + k2 * PITCH + wn * 32 + y * 16, PITCH);
            #pragma unroll
            for (int x = 0; x < 4; ++x)
                #pragma unroll
                for (int y = 0; y < 2; ++y)
                    wmma::mma_sync(acc[x][y], a[x], bf[y], acc[x][y]);
        }
    }

    // ---- epilogue: C into smem (aliases pipeline buffers), kill-test ----
    __syncthreads();
    float* Cs = (float*)dyn;   // 128 x 132
    #pragma unroll
    for (int x = 0; x < 4; ++x)
        #pragma unroll
        for (int y = 0; y < 2; ++y)
            wmma::store_matrix_sync(Cs + (wm * 64 + x * 16) * 132 + wn * 32 + y * 16,
                                    acc[x][y], 132, wmma::mem_row_major);
    __syncthreads();

    const float inv = 1.0f / (SS - 1);
    for (int idx = t; idx < 128 * 128; idx += 256) {
        int ti = idx >> 7, tj = idx & 127;
        int gi = i0 + ti, gj = j0 + tj;
        if (gi >= gj) continue;
        float cov = (Cs[ti * 132 + tj] - (float)SS * s_mi[ti] * s_mj[tj]) * inv;
        if (cov * cov > 0.25f * s_vi[ti] * s_vj[tj]) {
            g_keep[b * DD + gi] = 0.0f;
            g_keep[b * DD + gj] = 0.0f;
        }
    }
}

// =====================================================================
// Kernel 4: out = x * keep[b,d]
// =====================================================================
__global__ void __launch_bounds__(256) apply_kernel(const float* __restrict__ x,
                                                    float* __restrict__ out) {
    size_t idx = (size_t)blockIdx.x * blockDim.x + threadIdx.x;
    size_t e = idx * 4;
    int d = (int)(e & (DD - 1));
    int b = (int)(e / ((size_t)SS * DD));
    float4 v = ((const float4*)x)[idx];
    float4 k = *(const float4*)(g_keep + b * DD + d);
    v.x *= k.x; v.y *= k.y; v.z *= k.z; v.w *= k.w;
    ((float4*)out)[idx] = v;
}

// =====================================================================
extern "C" void kernel_launch(void* const* d_in, const int* in_sizes, int n_in,
                              void* d_out, int out_size) {
    const float* x = (const float*)d_in[0];
    float* out = (float*)d_out;

    cudaFuncSetAttribute(gram_kernel, cudaFuncAttributeMaxDynamicSharedMemorySize, DYNSMEM);

    stats_convert_kernel<<<BB * CH, 256>>>(x);
    finalize_stats_kernel<<<(BB * DD) / 256, 256>>>();
    gram_kernel<<<dim3(36, BB), 256, DYNSMEM>>>();
    apply_kernel<<<(size_t)(BB * SS * DD / 4) / 256, 256>>>(x, out);
}

// round 16
// speedup vs baseline: 1.0029x; 1.0029x over previous
#include <cuda_runtime.h>
#include <cuda_bf16.h>
#include <mma.h>
#include <cstdint>

using namespace nvcuda;

#define BB 32
#define SS 2048
#define DD 1024
#define CH 16
#define SC (SS/CH)

// ---------------- device scratch (no allocs allowed) ----------------
__device__ __nv_bfloat16 g_xb[(size_t)BB * SS * DD];   // bf16 x, row-major [b][s][d]
__device__ float g_psum[BB * CH * DD];
__device__ float g_psq [BB * CH * DD];
__device__ float g_mean[BB * DD];
__device__ float g_var [BB * DD];
__device__ float g_keep[BB * DD];

__device__ __forceinline__ uint32_t smem_u32(const void* p) {
    uint32_t a;
    asm("{ .reg .u64 t; cvta.to.shared.u64 t, %1; cvt.u32.u64 %0, t; }" : "=r"(a) : "l"(p));
    return a;
}
#define CP_ASYNC16(sm, gm) \
    asm volatile("cp.async.cg.shared.global [%0], [%1], 16;" :: "r"(sm), "l"(gm) : "memory")
#define CP_COMMIT()   asm volatile("cp.async.commit_group;" ::: "memory")
#define CP_WAIT(n)    asm volatile("cp.async.wait_group %0;" :: "n"(n) : "memory")

// =====================================================================
// Kernel 1: per-(b, s-chunk) column partial sums + fp32->bf16 convert
// =====================================================================
__global__ void __launch_bounds__(256) stats_convert_kernel(const float* __restrict__ x) {
    int b = blockIdx.x / CH;
    int c = blockIdx.x % CH;
    int d0 = threadIdx.x * 4;

    float s0 = 0.f, s1 = 0.f, s2 = 0.f, s3 = 0.f;
    float q0 = 0.f, q1 = 0.f, q2 = 0.f, q3 = 0.f;

    #pragma unroll 4
    for (int r = 0; r < SC; ++r) {
        size_t off = ((size_t)b * SS + (size_t)c * SC + r) * DD + d0;
        float4 v = *(const float4*)(x + off);
        s0 += v.x; s1 += v.y; s2 += v.z; s3 += v.w;
        q0 += v.x * v.x; q1 += v.y * v.y; q2 += v.z * v.z; q3 += v.w * v.w;
        __nv_bfloat162 lo = __floats2bfloat162_rn(v.x, v.y);
        __nv_bfloat162 hi = __floats2bfloat162_rn(v.z, v.w);
        uint2 pk;
        pk.x = *(const unsigned int*)&lo;
        pk.y = *(const unsigned int*)&hi;
        *(uint2*)(g_xb + off) = pk;
    }
    int p = (b * CH + c) * DD + d0;
    *(float4*)(g_psum + p) = make_float4(s0, s1, s2, s3);
    *(float4*)(g_psq  + p) = make_float4(q0, q1, q2, q3);
}

// =====================================================================
// Kernel 2: reduce partials -> mean/var, init keep=1
// =====================================================================
__global__ void finalize_stats_kernel() {
    int i = blockIdx.x * 256 + threadIdx.x;
    int b = i >> 10, d = i & 1023;
    float s = 0.f, q = 0.f;
    #pragma unroll
    for (int c = 0; c < CH; ++c) {
        s += g_psum[(b * CH + c) * DD + d];
        q += g_psq [(b * CH + c) * DD + d];
    }
    float mean = s * (1.0f / SS);
    float var  = (q - (float)SS * mean * mean) * (1.0f / (SS - 1));
    g_mean[i] = mean; g_var[i] = var; g_keep[i] = 1.0f;
}

// =====================================================================
// Kernel 3: HMMA Gram, 128x128 tiles, 4-stage cp.async pipeline
//   8 warps in 2x4 grid; warp tile = 64(i) x 32(j)
//   smem stage: A[32k][128i] + B[32k][128j], pitch 136 bf16 (272B)
// =====================================================================
#define KB      32                      // k per slab
#define NSLAB   (SS / KB)               // 64
#define PITCH   136                     // bf16 elems per smem row
#define TBYTES  (KB * PITCH * 2)        // 8704 per tile
#define STAGEB  (2 * TBYTES)            // 17408
#define STAGES  4
#define DYNSMEM (STAGES * STAGEB)       // 69632 (C tile 128*132*4=67584 aliases)

// 36 upper-triangle pairs of 128-wide tiles over D=1024 (8 tiles)
__constant__ int c_bi[36] = {0, 0,1, 0,1,2, 0,1,2,3, 0,1,2,3,4, 0,1,2,3,4,5,
                             0,1,2,3,4,5,6, 0,1,2,3,4,5,6,7};
__constant__ int c_bj[36] = {0, 1,1, 2,2,2, 3,3,3,3, 4,4,4,4,4, 5,5,5,5,5,5,
                             6,6,6,6,6,6,6, 7,7,7,7,7,7,7,7};

__global__ void __launch_bounds__(256, 2) gram_kernel() {
    extern __shared__ __align__(16) uint8_t dyn[];
    __shared__ float s_mi[128], s_vi[128], s_mj[128], s_vj[128];

    int t = threadIdx.x, wid = t >> 5;
    int wm = wid >> 2;              // 0..1 -> 64-row half
    int wn = wid & 3;               // 0..3 -> 32-col quarter
    int b  = blockIdx.y;
    int i0 = c_bi[blockIdx.x] * 128;
    int j0 = c_bj[blockIdx.x] * 128;

    if (t < 128) {
        s_mi[t] = g_mean[b * DD + i0 + t];
        s_vi[t] = g_var [b * DD + i0 + t];
        s_mj[t] = g_mean[b * DD + j0 + t];
        s_vj[t] = g_var [b * DD + j0 + t];
    }

    const __nv_bfloat16* xb = g_xb + (size_t)b * SS * DD;
    uint32_t sbase = smem_u32(dyn);

    // per-thread chunk mapping: 4 chunks of 16B, c = i*256 + t
    //   tile = c>>9 (0=A/bi, 1=B/bj), r = (c>>4)&31, ch = c&15
    auto issue_slab = [&](int kc) {
        #pragma unroll
        for (int i = 0; i < 4; ++i) {
            int c    = i * 256 + t;
            int tile = c >> 9;
            int r    = (c >> 4) & 31;
            int ch   = c & 15;
            int dbase = (tile ? j0 : i0);
            const __nv_bfloat16* gp = xb + (size_t)(kc * KB + r) * DD + dbase + ch * 8;
            uint32_t sp = sbase + (uint32_t)((kc & (STAGES - 1)) * STAGEB
                                             + tile * TBYTES + r * (PITCH * 2) + ch * 16);
            CP_ASYNC16(sp, gp);
        }
        CP_COMMIT();
    };

    issue_slab(0); issue_slab(1); issue_slab(2);

    wmma::fragment<wmma::accumulator, 16, 16, 16, float> acc[4][2];
    #pragma unroll
    for (int x = 0; x < 4; ++x)
        #pragma unroll
        for (int y = 0; y < 2; ++y) wmma::fill_fragment(acc[x][y], 0.0f);

    for (int kc = 0; kc < NSLAB; ++kc) {
        CP_WAIT(2);
        __syncthreads();
        if (kc + 3 < NSLAB) issue_slab(kc + 3);

        const __nv_bfloat16* As = (const __nv_bfloat16*)(dyn + (kc & (STAGES - 1)) * STAGEB);
        const __nv_bfloat16* Bs = As + KB * PITCH;

        #pragma unroll
        for (int k2 = 0; k2 < KB; k2 += 16) {
            wmma::fragment<wmma::matrix_a, 16, 16, 16, __nv_bfloat16, wmma::col_major> a[4];
            wmma::fragment<wmma::matrix_b, 16, 16, 16, __nv_bfloat16, wmma::row_major> bf[2];
            #pragma unroll
            for (int x = 0; x < 4; ++x)
                wmma::load_matrix_sync(a[x], As + k2 * PITCH + wm * 64 + x * 16, PITCH);
            #pragma unroll
            for (int y = 0; y < 2; ++y)
                wmma::load_matrix_sync(bf[y], Bs + k2 * PITCH + wn * 32 + y * 16, PITCH);
            #pragma unroll
            for (int x = 0; x < 4; ++x)
                #pragma unroll
                for (int y = 0; y < 2; ++y)
                    wmma::mma_sync(acc[x][y], a[x], bf[y], acc[x][y]);
        }
    }

    // ---- epilogue: C into smem (aliases pipeline buffers), kill-test ----
    __syncthreads();
    float* Cs = (float*)dyn;   // 128 x 132
    #pragma unroll
    for (int x = 0; x < 4; ++x)
        #pragma unroll
        for (int y = 0; y < 2; ++y)
            wmma::store_matrix_sync(Cs + (wm * 64 + x * 16) * 132 + wn * 32 + y * 16,
                                    acc[x][y], 132, wmma::mem_row_major);
    __syncthreads();

    const float inv = 1.0f / (SS - 1);
    for (int idx = t; idx < 128 * 128; idx += 256) {
        int ti = idx >> 7, tj = idx & 127;
        int gi = i0 + ti, gj = j0 + tj;
        if (gi >= gj) continue;
        float cov = (Cs[ti * 132 + tj] - (float)SS * s_mi[ti] * s_mj[tj]) * inv;
        if (cov * cov > 0.25f * s_vi[ti] * s_vj[tj]) {
            g_keep[b * DD + gi] = 0.0f;
            g_keep[b * DD + gj] = 0.0f;
        }
    }
}

// =====================================================================
// Kernel 4: out = x * keep[b,d]
// =====================================================================
__global__ void __launch_bounds__(256) apply_kernel(const float* __restrict__ x,
                                                    float* __restrict__ out) {
    size_t idx = (size_t)blockIdx.x * blockDim.x + threadIdx.x;
    size_t e = idx * 4;
    int d = (int)(e & (DD - 1));
    int b = (int)(e / ((size_t)SS * DD));
    float4 v = ((const float4*)x)[idx];
    float4 k = *(const float4*)(g_keep + b * DD + d);
    v.x *= k.x; v.y *= k.y; v.z *= k.z; v.w *= k.w;
    ((float4*)out)[idx] = v;
}

// =====================================================================
extern "C" void kernel_launch(void* const* d_in, const int* in_sizes, int n_in,
                              void* d_out, int out_size) {
    const float* x = (const float*)d_in[0];
    float* out = (float*)d_out;

    cudaFuncSetAttribute(gram_kernel, cudaFuncAttributeMaxDynamicSharedMemorySize, DYNSMEM);

    stats_convert_kernel<<<BB * CH, 256>>>(x);
    finalize_stats_kernel<<<(BB * DD) / 256, 256>>>();
    gram_kernel<<<dim3(36, BB), 256, DYNSMEM>>>();
    apply_kernel<<<(size_t)(BB * SS * DD / 4) / 256, 256>>>(x, out);
}

// round 17
// speedup vs baseline: 1.1538x; 1.1505x over previous
#include <cuda_runtime.h>
#include <cuda_bf16.h>
#include <cstdint>

#define BB 32
#define SS 2048
#define DD 1024
#define CH 16
#define SC (SS/CH)

// ---------------- device scratch (no allocs allowed) ----------------
__device__ __nv_bfloat16 g_xb[(size_t)BB * SS * DD];   // bf16 x, row-major [b][s][d]
__device__ float g_psum[BB * CH * DD];
__device__ float g_psq [BB * CH * DD];
__device__ float g_mean[BB * DD];
__device__ float g_var [BB * DD];
__device__ float g_keep[BB * DD];

__device__ __forceinline__ uint32_t smem_u32(const void* p) {
    uint32_t a;
    asm("{ .reg .u64 t; cvta.to.shared.u64 t, %1; cvt.u32.u64 %0, t; }" : "=r"(a) : "l"(p));
    return a;
}
#define CP_ASYNC16(sm, gm) \
    asm volatile("cp.async.cg.shared.global [%0], [%1], 16;" :: "r"(sm), "l"(gm) : "memory")
#define CP_COMMIT()   asm volatile("cp.async.commit_group;" ::: "memory")
#define CP_WAIT(n)    asm volatile("cp.async.wait_group %0;" :: "n"(n) : "memory")

#define LDSM4T(r, addr) \
    asm volatile("ldmatrix.sync.aligned.m8n8.x4.trans.shared.b16 {%0,%1,%2,%3}, [%4];" \
        : "=r"((r)[0]), "=r"((r)[1]), "=r"((r)[2]), "=r"((r)[3]) : "r"(addr))

#define MMA16816(d, a, bv0, bv1) \
    asm volatile("mma.sync.aligned.m16n8k16.row.col.f32.bf16.bf16.f32 " \
        "{%0,%1,%2,%3}, {%4,%5,%6,%7}, {%8,%9}, {%0,%1,%2,%3};" \
        : "+f"((d)[0]), "+f"((d)[1]), "+f"((d)[2]), "+f"((d)[3]) \
        : "r"((a)[0]), "r"((a)[1]), "r"((a)[2]), "r"((a)[3]), "r"(bv0), "r"(bv1))

// =====================================================================
// Kernel 1: per-(b, s-chunk) column partial sums + fp32->bf16 convert
// =====================================================================
__global__ void __launch_bounds__(256) stats_convert_kernel(const float* __restrict__ x) {
    int b = blockIdx.x / CH;
    int c = blockIdx.x % CH;
    int d0 = threadIdx.x * 4;

    float s0 = 0.f, s1 = 0.f, s2 = 0.f, s3 = 0.f;
    float q0 = 0.f, q1 = 0.f, q2 = 0.f, q3 = 0.f;

    #pragma unroll 4
    for (int r = 0; r < SC; ++r) {
        size_t off = ((size_t)b * SS + (size_t)c * SC + r) * DD + d0;
        float4 v = *(const float4*)(x + off);
        s0 += v.x; s1 += v.y; s2 += v.z; s3 += v.w;
        q0 += v.x * v.x; q1 += v.y * v.y; q2 += v.z * v.z; q3 += v.w * v.w;
        __nv_bfloat162 lo = __floats2bfloat162_rn(v.x, v.y);
        __nv_bfloat162 hi = __floats2bfloat162_rn(v.z, v.w);
        uint2 pk;
        pk.x = *(const unsigned int*)&lo;
        pk.y = *(const unsigned int*)&hi;
        *(uint2*)(g_xb + off) = pk;
    }
    int p = (b * CH + c) * DD + d0;
    *(float4*)(g_psum + p) = make_float4(s0, s1, s2, s3);
    *(float4*)(g_psq  + p) = make_float4(q0, q1, q2, q3);
}

// =====================================================================
// Kernel 2: reduce partials -> mean/var, init keep=1
// =====================================================================
__global__ void finalize_stats_kernel() {
    int i = blockIdx.x * 256 + threadIdx.x;
    int b = i >> 10, d = i & 1023;
    float s = 0.f, q = 0.f;
    #pragma unroll
    for (int c = 0; c < CH; ++c) {
        s += g_psum[(b * CH + c) * DD + d];
        q += g_psq [(b * CH + c) * DD + d];
    }
    float mean = s * (1.0f / SS);
    float var  = (q - (float)SS * mean * mean) * (1.0f / (SS - 1));
    g_mean[i] = mean; g_var[i] = var; g_keep[i] = 1.0f;
}

// =====================================================================
// Kernel 3: raw-MMA Gram.  CTA tile 128(i) x 256(j), K=2048.
//   8 warps (2 i-halves x 4 j-quarters), warp tile 64x64.
//   smem stage: A[32k][128i] pitch 272B + B[32k][256j] pitch 528B.
//   ldmatrix.x4.trans fragments, mma.m16n8k16 bf16->fp32.
//   Epilogue kill-test straight from accumulator registers.
// =====================================================================
#define KB      32
#define NSLAB   (SS / KB)               // 64
#define APITCHB 272                     // 128 bf16 + 8 pad
#define BPITCHB 528                     // 256 bf16 + 8 pad
#define ABYTES  (KB * APITCHB)          // 8704
#define BBYTES  (KB * BPITCHB)          // 16896
#define STAGEB  (ABYTES + BBYTES)       // 25600
#define STAGES  4
#define DYNSMEM (STAGES * STAGEB)       // 102400

// 20 (bi:128-tile, bj:256-tile) pairs covering the strict upper triangle
__constant__ int c_bi[20] = {0,1, 0,1,2,3, 0,1,2,3,4,5, 0,1,2,3,4,5,6,7};
__constant__ int c_bj[20] = {0,0, 1,1,1,1, 2,2,2,2,2,2, 3,3,3,3,3,3,3,3};

__global__ void __launch_bounds__(256, 1) gram_kernel() {
    extern __shared__ __align__(16) uint8_t dyn[];
    __shared__ float s_mi[128], s_vi[128], s_mj[256], s_vj[256];

    int t = threadIdx.x, wid = t >> 5, lane = t & 31;
    int wm = wid >> 2;          // 0..1 -> 64-row half (i)
    int wn = wid & 3;           // 0..3 -> 64-col quarter (j)
    int b  = blockIdx.y;
    int i0 = c_bi[blockIdx.x] * 128;
    int j0 = c_bj[blockIdx.x] * 256;

    if (t < 128) { s_mi[t] = g_mean[b * DD + i0 + t]; s_vi[t] = g_var[b * DD + i0 + t]; }
    s_mj[t] = g_mean[b * DD + j0 + t];
    s_vj[t] = g_var [b * DD + j0 + t];

    const __nv_bfloat16* xb = g_xb + (size_t)b * SS * DD;
    uint32_t sbase = smem_u32(dyn);

    // cp.async slab fill: 512 A-chunks + 1024 B-chunks of 16B, 6 per thread
    auto issue_slab = [&](int kc) {
        uint32_t st = sbase + (uint32_t)((kc & (STAGES - 1)) * STAGEB);
        #pragma unroll
        for (int i = 0; i < 2; ++i) {               // A: c = i*256 + t in [0,512)
            int c = i * 256 + t;
            int r = c >> 4, ch = c & 15;
            const __nv_bfloat16* gp = xb + (size_t)(kc * KB + r) * DD + i0 + ch * 8;
            CP_ASYNC16(st + (uint32_t)(r * APITCHB + ch * 16), gp);
        }
        #pragma unroll
        for (int i = 0; i < 4; ++i) {               // B: c2 = i*256 + t in [0,1024)
            int c2 = i * 256 + t;
            int r = c2 >> 5, ch = c2 & 31;
            const __nv_bfloat16* gp = xb + (size_t)(kc * KB + r) * DD + j0 + ch * 8;
            CP_ASYNC16(st + (uint32_t)(ABYTES + r * BPITCHB + ch * 16), gp);
        }
        CP_COMMIT();
    };

    issue_slab(0); issue_slab(1); issue_slab(2);

    // per-lane ldmatrix base offsets (bytes)
    //   A: kr = (l&7) + ((l&16)>>1), icol = (l&8)        [+ wm*64 + x*16]
    //   B: kr = (l&7) + (l&8),       jcol = (l&16)>>1    [+ wn*64 + y*16]
    uint32_t a_lane = (uint32_t)(((lane & 7) + ((lane & 16) >> 1)) * APITCHB
                                 + (wm * 64 + (lane & 8)) * 2);
    uint32_t b_lane = (uint32_t)(((lane & 7) + (lane & 8)) * BPITCHB
                                 + (wn * 64 + ((lane & 16) >> 1)) * 2);

    float acc[4][8][4] = {};

    for (int kc = 0; kc < NSLAB; ++kc) {
        CP_WAIT(2);
        __syncthreads();
        if (kc + 3 < NSLAB) issue_slab(kc + 3);

        uint32_t Ab = sbase + (uint32_t)((kc & (STAGES - 1)) * STAGEB) + a_lane;
        uint32_t Bb = sbase + (uint32_t)((kc & (STAGES - 1)) * STAGEB) + ABYTES + b_lane;

        #pragma unroll
        for (int k2 = 0; k2 < 2; ++k2) {
            uint32_t af[4][4], bf[4][4];
            #pragma unroll
            for (int x = 0; x < 4; ++x)
                LDSM4T(af[x], Ab + (uint32_t)(k2 * 16 * APITCHB + x * 32));
            #pragma unroll
            for (int y = 0; y < 4; ++y)
                LDSM4T(bf[y], Bb + (uint32_t)(k2 * 16 * BPITCHB + y * 32));
            #pragma unroll
            for (int x = 0; x < 4; ++x)
                #pragma unroll
                for (int y = 0; y < 4; ++y) {
                    MMA16816(acc[x][2 * y],     af[x], bf[y][0], bf[y][1]);
                    MMA16816(acc[x][2 * y + 1], af[x], bf[y][2], bf[y][3]);
                }
        }
    }

    // ---- epilogue: kill-test from registers ----
    // acc element map (m16n8): c0:(r,c) c1:(r,c+1) c2:(r+8,c) c3:(r+8,c+1)
    //   r = lane>>2, c = 2*(lane&3)
    const float inv = 1.0f / (SS - 1);
    int rq = lane >> 2, cq = 2 * (lane & 3);
    #pragma unroll
    for (int x = 0; x < 4; ++x) {
        int li = wm * 64 + x * 16 + rq;
        float mi0 = s_mi[li],     vi0 = s_vi[li];
        float mi1 = s_mi[li + 8], vi1 = s_vi[li + 8];
        int gi0 = i0 + li, gi1 = gi0 + 8;
        #pragma unroll
        for (int nt = 0; nt < 8; ++nt) {
            int lj = wn * 64 + nt * 8 + cq;
            #pragma unroll
            for (int e = 0; e < 2; ++e) {
                int gj = j0 + lj + e;
                float mj = s_mj[lj + e], vj = s_vj[lj + e];
                if (gj > gi0) {
                    float cov = (acc[x][nt][e] - (float)SS * mi0 * mj) * inv;
                    if (cov * cov > 0.25f * vi0 * vj) {
                        g_keep[b * DD + gi0] = 0.0f;
                        g_keep[b * DD + gj]  = 0.0f;
                    }
                }
                if (gj > gi1) {
                    float cov = (acc[x][nt][2 + e] - (float)SS * mi1 * mj) * inv;
                    if (cov * cov > 0.25f * vi1 * vj) {
                        g_keep[b * DD + gi1] = 0.0f;
                        g_keep[b * DD + gj]  = 0.0f;
                    }
                }
            }
        }
    }
}

// =====================================================================
// Kernel 4: out = x * keep[b,d]
// =====================================================================
__global__ void __launch_bounds__(256) apply_kernel(const float* __restrict__ x,
                                                    float* __restrict__ out) {
    size_t idx = (size_t)blockIdx.x * blockDim.x + threadIdx.x;
    size_t e = idx * 4;
    int d = (int)(e & (DD - 1));
    int b = (int)(e / ((size_t)SS * DD));
    float4 v = ((const float4*)x)[idx];
    float4 k = *(const float4*)(g_keep + b * DD + d);
    v.x *= k.x; v.y *= k.y; v.z *= k.z; v.w *= k.w;
    ((float4*)out)[idx] = v;
}

// =====================================================================
extern "C" void kernel_launch(void* const* d_in, const int* in_sizes, int n_in,
                              void* d_out, int out_size) {
    const float* x = (const float*)d_in[0];
    float* out = (float*)d_out;

    cudaFuncSetAttribute(gram_kernel, cudaFuncAttributeMaxDynamicSharedMemorySize, DYNSMEM);

    stats_convert_kernel<<<BB * CH, 256>>>(x);
    finalize_stats_kernel<<<(BB * DD) / 256, 256>>>();
    gram_kernel<<<dim3(20, BB), 256, DYNSMEM>>>();
    apply_kernel<<<(size_t)(BB * SS * DD / 4) / 256, 256>>>(x, out);
}